// round 5
// baseline (speedup 1.0000x reference)
#include <cuda_runtime.h>
#include <cuda.h>
#include <cuda_bf16.h>
#include <math_constants.h>

#define N_TOKENS   8192
#define QUANT_DIM  8192
#define OUTPUT_DIM 1024

// ---------------------------------------------------------------------------
// mbarrier / TMA helpers
// ---------------------------------------------------------------------------
__device__ __forceinline__ uint32_t smem_u32(const void* p) {
    return (uint32_t)__cvta_generic_to_shared(p);
}

__device__ __forceinline__ void mbar_init(uint32_t mb, uint32_t count) {
    asm volatile("mbarrier.init.shared::cta.b64 [%0], %1;"
                 :: "r"(mb), "r"(count) : "memory");
}

__device__ __forceinline__ void mbar_expect_tx(uint32_t mb, uint32_t bytes) {
    asm volatile("mbarrier.arrive.expect_tx.shared::cta.b64 _, [%0], %1;"
                 :: "r"(mb), "r"(bytes) : "memory");
}

__device__ __forceinline__ void mbar_wait_parity0(uint32_t mb) {
    asm volatile(
        "{\n\t"
        ".reg .pred P;\n\t"
        "WAIT_%=:\n\t"
        "mbarrier.try_wait.parity.shared::cta.b64 P, [%0], 0, 0x989680;\n\t"
        "@P bra DONE_%=;\n\t"
        "bra WAIT_%=;\n\t"
        "DONE_%=:\n\t"
        "}"
        :: "r"(mb) : "memory");
}

__device__ __forceinline__ void tma_load_2d(uint32_t smem_dst,
                                            const CUtensorMap* tmap,
                                            int c0, int c1, uint32_t mb) {
    asm volatile(
        "cp.async.bulk.tensor.2d.shared::cta.global.tile.mbarrier::complete_tx::bytes "
        "[%0], [%1, {%2, %3}], [%4];"
        :: "r"(smem_dst), "l"(tmap), "r"(c0), "r"(c1), "r"(mb)
        : "memory");
}

// ---------------------------------------------------------------------------
// Fused kernel: one block per token row.
//  Phase 1: argmax over x[row]          (first-index tie-break, jnp semantics)
//  Phase 2: TMA-gather column idx of W: 4x cp.async.bulk.tensor.2d, box
//           (8 cols x 256 rows) = the 32B sectors containing W[:, idx].
//           The TMA engine does the 1024 strided fetches -> zero L1 wavefront
//           contention with the x stream. Then smem pick-out + coalesced
//           streaming stores.
// ---------------------------------------------------------------------------
__global__ __launch_bounds__(256) void argmax_tma_gather_kernel(
    const float* __restrict__ x,
    const __grid_constant__ CUtensorMap tmap,
    float* __restrict__ out)
{
    __shared__ alignas(128) float wtile[8 * OUTPUT_DIM];   // 32 KB
    __shared__ float s_val[8];
    __shared__ int   s_idx[8];
    __shared__ int   s_result;
    __shared__ alignas(8) unsigned long long mbar;

    const int row  = blockIdx.x;
    const int tid  = threadIdx.x;
    const int lane = tid & 31;
    const int warp = tid >> 5;

    if (tid == 0) {
        mbar_init(smem_u32(&mbar), 1);
        asm volatile("fence.proxy.async.shared::cta;" ::: "memory");
    }

    // ---- Phase 1: argmax (8192 floats = 2048 float4, 8 iters/thread) ----
    const float4* __restrict__ xr =
        reinterpret_cast<const float4*>(x + (size_t)row * QUANT_DIM);

    float best = -CUDART_INF_F;
    int   bidx = 0;

    #pragma unroll
    for (int it = 0; it < 8; ++it) {
        const int i = tid + it * 256;
        const float4 v = __ldcs(&xr[i]);          // streaming: keep W in L2
        const float vm = fmaxf(fmaxf(v.x, v.y), fmaxf(v.z, v.w));
        if (vm > best) {                           // rare after warmup
            best = vm;
            const int base = i * 4;
            bidx = (v.x == vm) ? base
                 : (v.y == vm) ? base + 1
                 : (v.z == vm) ? base + 2
                 :               base + 3;         // first-equal = first index
        }
    }

    // warp reduce: value desc, index asc on exact tie
    #pragma unroll
    for (int off = 16; off > 0; off >>= 1) {
        float ov = __shfl_down_sync(0xFFFFFFFFu, best, off);
        int   oi = __shfl_down_sync(0xFFFFFFFFu, bidx, off);
        if (ov > best || (ov == best && oi < bidx)) { best = ov; bidx = oi; }
    }
    if (lane == 0) { s_val[warp] = best; s_idx[warp] = bidx; }
    __syncthreads();

    if (warp == 0) {
        best = (lane < 8) ? s_val[lane] : -CUDART_INF_F;
        bidx = (lane < 8) ? s_idx[lane] : 0x7FFFFFFF;
        #pragma unroll
        for (int off = 4; off > 0; off >>= 1) {
            float ov = __shfl_down_sync(0xFFFFFFFFu, best, off);
            int   oi = __shfl_down_sync(0xFFFFFFFFu, bidx, off);
            if (ov > best || (ov == best && oi < bidx)) { best = ov; bidx = oi; }
        }
        if (lane == 0) s_result = bidx;
    }
    __syncthreads();

    // ---- Phase 2: TMA gather of W[:, idx] sectors ----
    const int idx = s_result;                      // uniform per block

    if (tid == 0) {
        const uint32_t mb  = smem_u32(&mbar);
        const uint32_t dst = smem_u32(wtile);
        mbar_expect_tx(mb, 8 * 256 * 4 * 4);       // 32768 bytes total
        const int c0 = idx & ~7;                   // sector-aligned column base
        #pragma unroll
        for (int s = 0; s < 4; ++s)
            tma_load_2d(dst + s * 8192, &tmap, c0, s * 256, mb);
    }

    mbar_wait_parity0(smem_u32(&mbar));

    // wtile[r*8 + k] = W[r][ (idx&~7) + k ];  value for out[row][c] is
    // wtile[c*8 + (idx&7)].
    const int off = idx & 7;
    float* __restrict__ dstrow = out + (size_t)row * OUTPUT_DIM;
    #pragma unroll
    for (int j = 0; j < 4; ++j) {
        const int c = tid + j * 256;
        __stcs(&dstrow[c], wtile[c * 8 + off]);    // coalesced streaming store
    }
}

// ---------------------------------------------------------------------------
typedef CUresult (*EncodeTiledFn)(
    CUtensorMap*, CUtensorMapDataType, cuuint32_t, void*,
    const cuuint64_t*, const cuuint64_t*, const cuuint32_t*, const cuuint32_t*,
    CUtensorMapInterleave, CUtensorMapSwizzle, CUtensorMapL2promotion,
    CUtensorMapFloatOOBfill);

extern "C" void kernel_launch(void* const* d_in, const int* in_sizes, int n_in,
                              void* d_out, int out_size)
{
    const float* x = (const float*)d_in[0];   // [8192, 8192] fp32
    const float* W = (const float*)d_in[1];   // [1024, 8192] fp32
    float* out = (float*)d_out;               // [8192, 1024] fp32

    // Resolve cuTensorMapEncodeTiled via the runtime (no -lcuda needed).
    static EncodeTiledFn encode_tiled = nullptr;
    if (!encode_tiled) {
        void* fn = nullptr;
        cudaDriverEntryPointQueryResult qres;
#if CUDART_VERSION >= 12050
        cudaGetDriverEntryPointByVersion("cuTensorMapEncodeTiled", &fn, 12000,
                                         cudaEnableDefault, &qres);
#else
        cudaGetDriverEntryPoint("cuTensorMapEncodeTiled", &fn,
                                cudaEnableDefault, &qres);
#endif
        encode_tiled = (EncodeTiledFn)fn;
    }

    // W viewed as 2D: dim0 = quant (8192, contiguous), dim1 = output (1024),
    // row stride 32 KB. Box = 8 cols (32 B) x 256 rows.
    CUtensorMap tmap;
    cuuint64_t dims[2]    = { QUANT_DIM, OUTPUT_DIM };
    cuuint64_t strides[1] = { (cuuint64_t)QUANT_DIM * sizeof(float) };
    cuuint32_t box[2]     = { 8, 256 };
    cuuint32_t estr[2]    = { 1, 1 };
    encode_tiled(&tmap, CU_TENSOR_MAP_DATA_TYPE_FLOAT32, 2, (void*)W,
                 dims, strides, box, estr,
                 CU_TENSOR_MAP_INTERLEAVE_NONE, CU_TENSOR_MAP_SWIZZLE_NONE,
                 CU_TENSOR_MAP_L2_PROMOTION_L2_128B,
                 CU_TENSOR_MAP_FLOAT_OOB_FILL_NONE);

    argmax_tma_gather_kernel<<<N_TOKENS, 256>>>(x, tmap, out);
}

// round 7
// speedup vs baseline: 1.1777x; 1.1777x over previous
#include <cuda_runtime.h>
#include <cuda_bf16.h>
#include <math_constants.h>

#define N_TOKENS   8192
#define QUANT_DIM  8192
#define OUTPUT_DIM 1024
#define N_SECTORS  (QUANT_DIM / 8)     // 1024 sectors of 8 columns (32B)

// Scratch (__device__ globals: allocation-free). Zero-initialized at load;
// g_cnt is re-zeroed by sector_gather every run (graph-replay invariant).
__device__ int g_cnt[N_SECTORS];
__device__ int g_list[(size_t)N_SECTORS * N_TOKENS];   // packed (row<<3)|off

// ---------------------------------------------------------------------------
// Kernel 1: pure streaming argmax, one block per row. First-index tie-break
// (jnp.argmax). Winner is pushed into its sector's token list.
// ---------------------------------------------------------------------------
__global__ __launch_bounds__(256) void argmax_rows_kernel(
    const float* __restrict__ x)
{
    const int row = blockIdx.x;
    const float4* __restrict__ xr =
        reinterpret_cast<const float4*>(x + (size_t)row * QUANT_DIM);

    float best = -CUDART_INF_F;
    int   bidx = 0;

    #pragma unroll
    for (int it = 0; it < 8; ++it) {
        const int i = threadIdx.x + it * 256;
        const float4 v = __ldcs(&xr[i]);           // streaming read
        const float vm = fmaxf(fmaxf(v.x, v.y), fmaxf(v.z, v.w));
        if (vm > best) {                            // rare after warmup
            best = vm;
            const int base = i * 4;
            bidx = (v.x == vm) ? base
                 : (v.y == vm) ? base + 1
                 : (v.z == vm) ? base + 2
                 :               base + 3;          // first-equal = first index
        }
    }

    // warp reduce: value desc, index asc on exact tie
    #pragma unroll
    for (int off = 16; off > 0; off >>= 1) {
        float ov = __shfl_down_sync(0xFFFFFFFFu, best, off);
        int   oi = __shfl_down_sync(0xFFFFFFFFu, bidx, off);
        if (ov > best || (ov == best && oi < bidx)) { best = ov; bidx = oi; }
    }

    __shared__ float s_val[8];
    __shared__ int   s_idx[8];
    const int lane = threadIdx.x & 31;
    const int warp = threadIdx.x >> 5;
    if (lane == 0) { s_val[warp] = best; s_idx[warp] = bidx; }
    __syncthreads();

    if (warp == 0) {
        best = (lane < 8) ? s_val[lane] : -CUDART_INF_F;
        bidx = (lane < 8) ? s_idx[lane] : 0x7FFFFFFF;
        #pragma unroll
        for (int off = 4; off > 0; off >>= 1) {
            float ov = __shfl_down_sync(0xFFFFFFFFu, best, off);
            int   oi = __shfl_down_sync(0xFFFFFFFFu, bidx, off);
            if (ov > best || (ov == best && oi < bidx)) { best = ov; bidx = oi; }
        }
        if (lane == 0) {
            const int sec  = bidx >> 3;
            const int slot = atomicAdd(&g_cnt[sec], 1);
            g_list[((size_t)sec << 13) + slot] = (row << 3) | (bidx & 7);
        }
    }
}

// ---------------------------------------------------------------------------
// Kernel 2: sector gather. Block s loads W[:, 8s:8s+8] (32 KB) ONCE into
// smem [8][1032] (padded: conflict-free column reads), then emits each
// listed token's output row with LDS.128 + coalesced streaming STG.128.
// One sector fetch serves ~8 tokens -> 8x fewer L1 wavefronts than
// per-token column gathers.
// ---------------------------------------------------------------------------
#define TPAD 1032   // 1024 + 8; TPAD*4 bytes = 4128, 16B-aligned rows

__global__ __launch_bounds__(256) void sector_gather_kernel(
    const float* __restrict__ W, float* __restrict__ out)
{
    __shared__ float tile[8 * TPAD];   // [k][r], k = col-in-sector, r = out dim
    __shared__ int   s_cnt;

    const int sec = blockIdx.x;
    const int tid = threadIdx.x;

    if (tid == 0) {
        s_cnt = g_cnt[sec];
        g_cnt[sec] = 0;                // self-reset for next graph replay
    }
    __syncthreads();
    const int cnt = s_cnt;
    if (cnt == 0) return;              // untouched sector: skip the 32 KB load

    // Load sector-column block: row r (output dim), 8 floats. float4 per
    // thread: k0 = (tid&1)*4, r = tid>>1, 128 rows per iteration.
    const int k0 = (tid & 1) * 4;
    #pragma unroll
    for (int it = 0; it < 8; ++it) {
        const int r = (tid >> 1) + it * 128;
        const float4 v = __ldcs(reinterpret_cast<const float4*>(
            W + (size_t)r * QUANT_DIM + sec * 8 + k0));
        tile[(k0 + 0) * TPAD + r] = v.x;
        tile[(k0 + 1) * TPAD + r] = v.y;
        tile[(k0 + 2) * TPAD + r] = v.z;
        tile[(k0 + 3) * TPAD + r] = v.w;
    }
    __syncthreads();

    // Emit output rows: thread tid covers floats [4*tid, 4*tid+4) of each row.
    for (int t = 0; t < cnt; ++t) {
        const int e     = g_list[((size_t)sec << 13) + t];  // uniform load
        const int token = e >> 3;
        const int off   = e & 7;
        const float4 v  = *reinterpret_cast<const float4*>(
            &tile[off * TPAD + tid * 4]);                   // conflict-free
        __stcs(reinterpret_cast<float4*>(
                   out + (size_t)token * OUTPUT_DIM) + tid, v);
    }
}

// ---------------------------------------------------------------------------
extern "C" void kernel_launch(void* const* d_in, const int* in_sizes, int n_in,
                              void* d_out, int out_size)
{
    const float* x = (const float*)d_in[0];   // [8192, 8192] fp32
    const float* W = (const float*)d_in[1];   // [1024, 8192] fp32
    float* out = (float*)d_out;               // [8192, 1024] fp32

    argmax_rows_kernel<<<N_TOKENS, 256>>>(x);
    sector_gather_kernel<<<N_SECTORS, 256>>>(W, out);
}

// round 8
// speedup vs baseline: 1.2160x; 1.0325x over previous
#include <cuda_runtime.h>
#include <cuda_bf16.h>
#include <math_constants.h>

#define N_TOKENS   8192
#define QUANT_DIM  8192
#define OUTPUT_DIM 1024
#define N_SECTORS  (QUANT_DIM / 8)        // 1024 sectors of 8 columns (32B)
#define N_SLICES   8                      // 128 output rows per slice
#define GATHER_BLOCKS (N_SECTORS * N_SLICES)

// Scratch (__device__ globals: allocation-free). Zero-initialized at load;
// g_cnt/g_done are reset by the last gather block every run (replay-safe).
__device__ int g_cnt[N_SECTORS];
__device__ int g_done;
__device__ int g_list[(size_t)N_SECTORS * N_TOKENS];   // packed (row<<3)|off

// ---------------------------------------------------------------------------
// Kernel 1: pure streaming argmax, one block per row. First-index tie-break
// (jnp.argmax). Winner pushed into its sector's token list (order arbitrary;
// output is order-invariant since each token owns its output row).
// ---------------------------------------------------------------------------
__global__ __launch_bounds__(256) void argmax_rows_kernel(
    const float* __restrict__ x)
{
    const int row = blockIdx.x;
    const float4* __restrict__ xr =
        reinterpret_cast<const float4*>(x + (size_t)row * QUANT_DIM);

    float best = -CUDART_INF_F;
    int   bidx = 0;

    #pragma unroll
    for (int it = 0; it < 8; ++it) {
        const int i = threadIdx.x + it * 256;
        const float4 v = __ldcs(&xr[i]);           // streaming read
        const float vm = fmaxf(fmaxf(v.x, v.y), fmaxf(v.z, v.w));
        if (vm > best) {                            // rare after warmup
            best = vm;
            const int base = i * 4;
            bidx = (v.x == vm) ? base
                 : (v.y == vm) ? base + 1
                 : (v.z == vm) ? base + 2
                 :               base + 3;          // first-equal = first index
        }
    }

    #pragma unroll
    for (int off = 16; off > 0; off >>= 1) {
        float ov = __shfl_down_sync(0xFFFFFFFFu, best, off);
        int   oi = __shfl_down_sync(0xFFFFFFFFu, bidx, off);
        if (ov > best || (ov == best && oi < bidx)) { best = ov; bidx = oi; }
    }

    __shared__ float s_val[8];
    __shared__ int   s_idx[8];
    const int lane = threadIdx.x & 31;
    const int warp = threadIdx.x >> 5;
    if (lane == 0) { s_val[warp] = best; s_idx[warp] = bidx; }
    __syncthreads();

    if (warp == 0) {
        best = (lane < 8) ? s_val[lane] : -CUDART_INF_F;
        bidx = (lane < 8) ? s_idx[lane] : 0x7FFFFFFF;
        #pragma unroll
        for (int off = 4; off > 0; off >>= 1) {
            float ov = __shfl_down_sync(0xFFFFFFFFu, best, off);
            int   oi = __shfl_down_sync(0xFFFFFFFFu, bidx, off);
            if (ov > best || (ov == best && oi < bidx)) { best = ov; bidx = oi; }
        }
        if (lane == 0) {
            const int sec  = bidx >> 3;
            const int slot = atomicAdd(&g_cnt[sec], 1);
            g_list[((size_t)sec << 13) + slot] = (row << 3) | (bidx & 7);
        }
    }
}

// ---------------------------------------------------------------------------
// Kernel 2: sliced sector gather. Block (sec, slice) loads the 128-row x
// 8-col slice W[slice*128 .. +128, sec*8 .. +8] into 4.5 KB padded smem
// (one float4 per thread), then for each token in the sector's list writes
// its 128-float output chunk (conflict-free LDS, 512B coalesced STG).
// 8192 blocks -> full occupancy; the counter reset uses the last-block-done
// pattern (arrival is ordered after the count read, so reset is race-free).
// ---------------------------------------------------------------------------
__global__ __launch_bounds__(256) void sector_slice_gather_kernel(
    const float* __restrict__ W, float* __restrict__ out)
{
    __shared__ float tile[128 * 9];    // [r_local][k], stride 9: conflict-free
    __shared__ int   s_cnt;
    __shared__ int   s_last;

    const int sec   = blockIdx.x;
    const int slice = blockIdx.y;
    const int tid   = threadIdx.x;

    // Load slice: thread t -> row t>>1 (2 threads/row), cols k0..k0+3.
    {
        const int r_loc = tid >> 1;
        const int k0    = (tid & 1) * 4;
        const int r_g   = slice * 128 + r_loc;
        const float4 v = __ldcs(reinterpret_cast<const float4*>(
            W + (size_t)r_g * QUANT_DIM + sec * 8 + k0));
        tile[r_loc * 9 + k0 + 0] = v.x;
        tile[r_loc * 9 + k0 + 1] = v.y;
        tile[r_loc * 9 + k0 + 2] = v.z;
        tile[r_loc * 9 + k0 + 3] = v.w;
    }

    if (tid == 0) {
        const int c = atomicAdd(&g_cnt[sec], 0);   // atomic read of count
        s_cnt = c;
        __threadfence();                           // order read before arrival
        const int d = atomicAdd(&g_done, 1);
        s_last = (d == GATHER_BLOCKS - 1);
    }
    __syncthreads();

    const int cnt   = s_cnt;
    const int half  = tid >> 7;        // two tokens per iteration
    const int c_loc = tid & 127;

    for (int t = half; t < cnt; t += 2) {
        const int e     = g_list[((size_t)sec << 13) + t];   // uniform/half
        const int token = e >> 3;
        const int off   = e & 7;
        const float val = tile[c_loc * 9 + off];             // stride 9: clean
        __stcs(&out[(size_t)token * OUTPUT_DIM + slice * 128 + c_loc], val);
    }

    // Last block (all counts already read by everyone): reset for next replay.
    if (s_last) {
        for (int i = tid; i < N_SECTORS; i += 256) g_cnt[i] = 0;
        if (tid == 0) g_done = 0;
    }
}

// ---------------------------------------------------------------------------
extern "C" void kernel_launch(void* const* d_in, const int* in_sizes, int n_in,
                              void* d_out, int out_size)
{
    const float* x = (const float*)d_in[0];   // [8192, 8192] fp32
    const float* W = (const float*)d_in[1];   // [1024, 8192] fp32
    float* out = (float*)d_out;               // [8192, 1024] fp32

    argmax_rows_kernel<<<N_TOKENS, 256>>>(x);
    sector_slice_gather_kernel<<<dim3(N_SECTORS, N_SLICES), 256>>>(W, out);
}

// round 9
// speedup vs baseline: 1.3489x; 1.1093x over previous
#include <cuda_runtime.h>
#include <cuda_bf16.h>
#include <math_constants.h>

#define N_TOKENS   8192
#define QUANT_DIM  8192
#define OUTPUT_DIM 1024
#define N_SECTORS  (QUANT_DIM / 8)        // 1024 sectors of 8 columns (32B)
#define N_SLICES   8                      // 128 output rows per slice
#define LIST_CHUNK 1024                   // smem staging chunk for token list

// Scratch (__device__ globals: allocation-free).
__device__ int g_cnt[N_SECTORS];
__device__ int g_list[(size_t)N_SECTORS * N_TOKENS];   // packed (row<<3)|off

// ---------------------------------------------------------------------------
// Kernel 0: reset sector counters. Launched first each replay -> argmax
// always starts from zeroed counters regardless of prior state.
// ---------------------------------------------------------------------------
__global__ __launch_bounds__(1024) void reset_kernel()
{
    g_cnt[threadIdx.x] = 0;
}

// ---------------------------------------------------------------------------
// Kernel 1: pure streaming argmax, one block per row. First-index tie-break
// (jnp.argmax). Winner pushed into its sector's token list (order arbitrary;
// output is order-invariant since each token owns its output row).
// ---------------------------------------------------------------------------
__global__ __launch_bounds__(256) void argmax_rows_kernel(
    const float* __restrict__ x)
{
    const int row = blockIdx.x;
    const float4* __restrict__ xr =
        reinterpret_cast<const float4*>(x + (size_t)row * QUANT_DIM);

    float best = -CUDART_INF_F;
    int   bidx = 0;

    #pragma unroll
    for (int it = 0; it < 8; ++it) {
        const int i = threadIdx.x + it * 256;
        const float4 v = __ldcs(&xr[i]);           // streaming read
        const float vm = fmaxf(fmaxf(v.x, v.y), fmaxf(v.z, v.w));
        if (vm > best) {                            // rare after warmup
            best = vm;
            const int base = i * 4;
            bidx = (v.x == vm) ? base
                 : (v.y == vm) ? base + 1
                 : (v.z == vm) ? base + 2
                 :               base + 3;          // first-equal = first index
        }
    }

    #pragma unroll
    for (int off = 16; off > 0; off >>= 1) {
        float ov = __shfl_down_sync(0xFFFFFFFFu, best, off);
        int   oi = __shfl_down_sync(0xFFFFFFFFu, bidx, off);
        if (ov > best || (ov == best && oi < bidx)) { best = ov; bidx = oi; }
    }

    __shared__ float s_val[8];
    __shared__ int   s_idx[8];
    const int lane = threadIdx.x & 31;
    const int warp = threadIdx.x >> 5;
    if (lane == 0) { s_val[warp] = best; s_idx[warp] = bidx; }
    __syncthreads();

    if (warp == 0) {
        best = (lane < 8) ? s_val[lane] : -CUDART_INF_F;
        bidx = (lane < 8) ? s_idx[lane] : 0x7FFFFFFF;
        #pragma unroll
        for (int off = 4; off > 0; off >>= 1) {
            float ov = __shfl_down_sync(0xFFFFFFFFu, best, off);
            int   oi = __shfl_down_sync(0xFFFFFFFFu, bidx, off);
            if (ov > best || (ov == best && oi < bidx)) { best = ov; bidx = oi; }
        }
        if (lane == 0) {
            const int sec  = bidx >> 3;
            const int slot = atomicAdd(&g_cnt[sec], 1);
            g_list[((size_t)sec << 13) + slot] = (row << 3) | (bidx & 7);
        }
    }
}

// ---------------------------------------------------------------------------
// Kernel 2: sliced sector gather. Block (sec, slice) loads the 128-row x
// 8-col slice W[slice*128 .. +128, sec*8 .. +8] into padded smem, stages the
// sector's token list into smem (overlapped with the W-slice fill), then
// emits each token's 128-float output chunk from smem only:
// LDS e -> LDS val -> 512B-coalesced streaming STG. No fences, no global
// atomics, no per-iteration global loads.
// ---------------------------------------------------------------------------
__global__ __launch_bounds__(256) void sector_slice_gather_kernel(
    const float* __restrict__ W, float* __restrict__ out)
{
    __shared__ float tile[128 * 9];     // [r_local][k], stride 9: conflict-free
    __shared__ int   s_list[LIST_CHUNK];
    __shared__ int   s_cnt;

    const int sec   = blockIdx.x;
    const int slice = blockIdx.y;
    const int tid   = threadIdx.x;

    // Issue the W-slice load immediately (2 threads/row, float4 each).
    const int r_loc = tid >> 1;
    const int k0    = (tid & 1) * 4;
    const float4 v = __ldcs(reinterpret_cast<const float4*>(
        W + (size_t)(slice * 128 + r_loc) * QUANT_DIM + sec * 8 + k0));

    if (tid == 0) s_cnt = g_cnt[sec];   // plain load: ordered by stream
    __syncthreads();
    const int cnt = s_cnt;
    if (cnt == 0) return;

    // Fill the tile (waits on v); list chunk loads overlap via scoreboarding.
    const int half  = tid >> 7;         // two tokens per emission iteration
    const int c_loc = tid & 127;

    bool tile_filled = false;
    for (int base = 0; base < cnt; base += LIST_CHUNK) {
        const int chunk = min(cnt - base, LIST_CHUNK);
        for (int j = tid; j < chunk; j += 256)
            s_list[j] = g_list[((size_t)sec << 13) + base + j];
        if (!tile_filled) {
            tile[r_loc * 9 + k0 + 0] = v.x;
            tile[r_loc * 9 + k0 + 1] = v.y;
            tile[r_loc * 9 + k0 + 2] = v.z;
            tile[r_loc * 9 + k0 + 3] = v.w;
            tile_filled = true;
        }
        __syncthreads();

        for (int t = half; t < chunk; t += 2) {
            const int e     = s_list[t];                  // smem broadcast
            const int token = e >> 3;
            const int off   = e & 7;
            const float val = tile[c_loc * 9 + off];      // stride 9: clean
            __stcs(&out[(size_t)token * OUTPUT_DIM + slice * 128 + c_loc], val);
        }
        __syncthreads();
    }
}

// ---------------------------------------------------------------------------
extern "C" void kernel_launch(void* const* d_in, const int* in_sizes, int n_in,
                              void* d_out, int out_size)
{
    const float* x = (const float*)d_in[0];   // [8192, 8192] fp32
    const float* W = (const float*)d_in[1];   // [1024, 8192] fp32
    float* out = (float*)d_out;               // [8192, 1024] fp32

    reset_kernel<<<1, 1024>>>();
    argmax_rows_kernel<<<N_TOKENS, 256>>>(x);
    sector_slice_gather_kernel<<<dim3(N_SECTORS, N_SLICES), 256>>>(W, out);
}